// round 5
// baseline (speedup 1.0000x reference)
#include <cuda_runtime.h>
#include <cuda_bf16.h>
#include <math.h>

#define NQ 512
#define DM 1024
#define NEL (NQ * DM)

// ---------------- scratch ----------------
__device__ float    g_txt[NEL];           // f32 (residual)
__device__ float    g_img[NEL];
__device__ unsigned g_txt_tf[NEL];        // tf32 copies (GEMM A inputs)
__device__ unsigned g_img_tf[NEL];
__device__ float    g_Q[2][NEL];
__device__ float    g_K[2][NEL];
__device__ float    g_V[2][NEL];
__device__ unsigned g_O_tf[2][NEL];       // attention out, tf32
__device__ unsigned g_w_tf[10][DM * DM];  // converted weights (tp_w uses 768*1024)
__device__ unsigned g_cap_tf[NQ * 768];   // converted captions
__device__ unsigned g_im_tf[NEL];         // converted images

__device__ __forceinline__ unsigned f2tf32(float x) {
    unsigned u;
    asm("cvt.rna.tf32.f32 %0, %1;" : "=r"(u) : "f"(x));
    return u;
}
__device__ __forceinline__ uint4 cvt4(float4 v) {
    return make_uint4(f2tf32(v.x), f2tf32(v.y), f2tf32(v.z), f2tf32(v.w));
}

// ---------------- bulk f32 -> tf32 conversion ----------------
struct ConvArgs {
    const float* src[12];
    unsigned*    dst[12];
    int          n4[12];   // element count / 4
};

__global__ __launch_bounds__(256) void conv_tf32_kernel(ConvArgs a) {
    const int z = blockIdx.y;
    const float4* __restrict__ s = (const float4*)a.src[z];
    uint4* __restrict__ d = (uint4*)a.dst[z];
    const int n4 = a.n4[z];
    for (int i = blockIdx.x * blockDim.x + threadIdx.x; i < n4; i += gridDim.x * blockDim.x)
        d[i] = cvt4(s[i]);
}

// ---------------------------------------------------------------------------
// tf32 tensor-core GEMM, inputs pre-converted to tf32.
// C = A(512xK) @ W(1024xK)^T + bias (+ resid)  [+ tf32 copy of C]
// BM=64, BN=64, BK=32, 128 threads (4 warps 2x2, warp tile 32x32).
// cp.async 3-stage pipeline, one __syncthreads per K-iter.
// ---------------------------------------------------------------------------
struct GemmArgs {
    const unsigned* A[6];
    const unsigned* W[6];
    const float*    bias[6];
    const float*    resid[6];
    float*          C[6];
    unsigned*       Ctf[6];
    int             K[6];
};

#define NSTAGE 3
#define TILE_WORDS (64 * 36)

__device__ __forceinline__ void cp_async16(unsigned smem_addr, const void* gptr) {
    asm volatile("cp.async.cg.shared.global [%0], [%1], 16;" :: "r"(smem_addr), "l"(gptr));
}
__device__ __forceinline__ void cp_commit() {
    asm volatile("cp.async.commit_group;");
}
__device__ __forceinline__ void cp_wait1() {
    asm volatile("cp.async.wait_group 1;");
}

extern __shared__ unsigned smem_dyn[];

__global__ __launch_bounds__(128) void gemm_tf32_kernel(GemmArgs args) {
    const int z = blockIdx.z;
    const unsigned* __restrict__ A = args.A[z];
    const unsigned* __restrict__ W = args.W[z];
    const float* __restrict__ bias = args.bias[z];
    const float* __restrict__ resid = args.resid[z];
    float* __restrict__ C = args.C[z];
    unsigned* __restrict__ Ctf = args.Ctf[z];
    const int K = args.K[z];
    const int T = K >> 5;

    const int m0 = blockIdx.y * 64;
    const int n0 = blockIdx.x * 64;

    unsigned* As = smem_dyn;                       // [NSTAGE][64][36]
    unsigned* Ws = smem_dyn + NSTAGE * TILE_WORDS;

    const int tid  = threadIdx.x;
    const int lane = tid & 31;
    const int wid  = tid >> 5;
    const int wm   = (wid & 1) * 32;
    const int wn   = (wid >> 1) * 32;
    const int g    = lane >> 2;
    const int tg   = lane & 3;

    // load mapping: f = tid + it*128 -> r = f>>3 (0..63), q = f&7 (8 x 16B per row)
    const int r0l = tid >> 3;      // base row (it adds 16)
    const int ql  = tid & 7;

    unsigned sA_base, sW_base;
    {
        unsigned base = (unsigned)__cvta_generic_to_shared(smem_dyn);
        sA_base = base + (r0l * 36 + ql * 4) * 4;
        sW_base = base + (NSTAGE * TILE_WORDS + r0l * 36 + ql * 4) * 4;
    }

    float acc[2][4][4];
#pragma unroll
    for (int mt = 0; mt < 2; mt++)
#pragma unroll
        for (int nt = 0; nt < 4; nt++)
#pragma unroll
            for (int r = 0; r < 4; r++) acc[mt][nt][r] = 0.f;

    // ---- issue loads for a stage ----
    auto issue = [&](int t, int st) {
        const int k0 = t * 32 + ql * 4;
        const unsigned soffA = sA_base + st * TILE_WORDS * 4;
        const unsigned soffW = sW_base + st * TILE_WORDS * 4;
#pragma unroll
        for (int it = 0; it < 4; it++) {
            cp_async16(soffA + it * 16 * 36 * 4, A + (m0 + r0l + it * 16) * K + k0);
            cp_async16(soffW + it * 16 * 36 * 4, W + (n0 + r0l + it * 16) * K + k0);
        }
    };

    // prologue: stages 0,1
    issue(0, 0); cp_commit();
    if (T > 1) issue(1, 1);
    cp_commit();

    int st = 0;
    for (int t = 0; t < T; t++) {
        cp_wait1();
        __syncthreads();

        if (t + 2 < T) issue(t + 2, (st + 2) % NSTAGE);
        cp_commit();

        const unsigned* Ab = As + st * TILE_WORDS;
        const unsigned* Wb = Ws + st * TILE_WORDS;

#pragma unroll
        for (int ks = 0; ks < 4; ks++) {
            const int kb = ks * 8;
            unsigned a[2][4], b[4][2];
#pragma unroll
            for (int mt = 0; mt < 2; mt++) {
                int row = wm + mt * 16 + g;
                a[mt][0] = Ab[row * 36 + kb + tg];
                a[mt][1] = Ab[(row + 8) * 36 + kb + tg];
                a[mt][2] = Ab[row * 36 + kb + tg + 4];
                a[mt][3] = Ab[(row + 8) * 36 + kb + tg + 4];
            }
#pragma unroll
            for (int nt = 0; nt < 4; nt++) {
                int n = wn + nt * 8 + g;
                b[nt][0] = Wb[n * 36 + kb + tg];
                b[nt][1] = Wb[n * 36 + kb + tg + 4];
            }
#pragma unroll
            for (int mt = 0; mt < 2; mt++)
#pragma unroll
                for (int nt = 0; nt < 4; nt++) {
                    asm volatile(
                        "mma.sync.aligned.m16n8k8.row.col.f32.tf32.tf32.f32 "
                        "{%0,%1,%2,%3}, {%4,%5,%6,%7}, {%8,%9}, {%0,%1,%2,%3};"
                        : "+f"(acc[mt][nt][0]), "+f"(acc[mt][nt][1]),
                          "+f"(acc[mt][nt][2]), "+f"(acc[mt][nt][3])
                        : "r"(a[mt][0]), "r"(a[mt][1]), "r"(a[mt][2]), "r"(a[mt][3]),
                          "r"(b[nt][0]), "r"(b[nt][1]));
                }
        }
        st = (st + 1) % NSTAGE;
    }

    // epilogue
#pragma unroll
    for (int mt = 0; mt < 2; mt++) {
#pragma unroll
        for (int nt = 0; nt < 4; nt++) {
            int row0 = m0 + wm + mt * 16 + g;
            int col  = n0 + wn + nt * 8 + tg * 2;
            float b0 = bias[col], b1 = bias[col + 1];
            float2 v0 = make_float2(acc[mt][nt][0] + b0, acc[mt][nt][1] + b1);
            float2 v1 = make_float2(acc[mt][nt][2] + b0, acc[mt][nt][3] + b1);
            if (resid) {
                float2 r0 = *(const float2*)(resid + row0 * DM + col);
                float2 r1 = *(const float2*)(resid + (row0 + 8) * DM + col);
                v0.x += r0.x; v0.y += r0.y;
                v1.x += r1.x; v1.y += r1.y;
            }
            *(float2*)(C + row0 * DM + col)       = v0;
            *(float2*)(C + (row0 + 8) * DM + col) = v1;
            if (Ctf) {
                *(uint2*)(Ctf + row0 * DM + col) = make_uint2(f2tf32(v0.x), f2tf32(v0.y));
                *(uint2*)(Ctf + (row0 + 8) * DM + col) = make_uint2(f2tf32(v1.x), f2tf32(v1.y));
            }
        }
    }
}

// ---------------------------------------------------------------------------
// sliding-window attention: one warp per (query, head); writes tf32 output
// ---------------------------------------------------------------------------
__global__ void swattn_kernel(const float* __restrict__ kb0, const float* __restrict__ vb0,
                              const float* __restrict__ kb1, const float* __restrict__ vb1) {
    const int a = blockIdx.y;
    const int i = blockIdx.x;
    const int h = threadIdx.x >> 5;
    const int lane = threadIdx.x & 31;

    const float* __restrict__ Q  = g_Q[a];
    const float* __restrict__ Kc = g_K[a];
    const float* __restrict__ Vc = g_V[a];
    const float* __restrict__ kb = a ? kb1 : kb0;
    const float* __restrict__ vb = a ? vb1 : vb0;

    __shared__ float sc[8][66];

    const float scale = 0.08838834764831845f;  // 1/sqrt(128)
    const int base = h * 128 + lane * 4;
    const float4 q4 = *(const float4*)(Q + i * DM + base);

    const int lo = i - 32;
    const int p_start = max(0, 32 - i);
    const int p_end   = min(66, 544 - i);
    const int invalid = 66 - (p_end - p_start);
    const int n_pad   = max(0, invalid - 2);

    for (int p = p_start; p < p_end; p++) {
        const float4 k4 = *(const float4*)(Kc + (lo + p) * DM + base);
        float part = q4.x * k4.x + q4.y * k4.y + q4.z * k4.z + q4.w * k4.w;
#pragma unroll
        for (int off = 16; off > 0; off >>= 1)
            part += __shfl_xor_sync(0xffffffffu, part, off);
        if (lane == 0) sc[h][p] = part * scale;
    }

    float s_pad = -1e30f;
    if (n_pad > 0) {
        const float4 kb4 = *(const float4*)(kb + base);
        float part = q4.x * kb4.x + q4.y * kb4.y + q4.z * kb4.z + q4.w * kb4.w;
#pragma unroll
        for (int off = 16; off > 0; off >>= 1)
            part += __shfl_xor_sync(0xffffffffu, part, off);
        s_pad = part * scale;
    }
    __syncwarp();

    float mloc = (n_pad > 0) ? s_pad : -1e30f;
    for (int p = p_start + lane; p < p_end; p += 32) mloc = fmaxf(mloc, sc[h][p]);
#pragma unroll
    for (int off = 16; off > 0; off >>= 1)
        mloc = fmaxf(mloc, __shfl_xor_sync(0xffffffffu, mloc, off));
    const float m = mloc;

    float dloc = 0.f;
    for (int p = p_start + lane; p < p_end; p += 32) {
        float e = expf(sc[h][p] - m);
        sc[h][p] = e;
        dloc += e;
    }
#pragma unroll
    for (int off = 16; off > 0; off >>= 1)
        dloc += __shfl_xor_sync(0xffffffffu, dloc, off);
    float w_pad = 0.f;
    if (n_pad > 0) w_pad = (float)n_pad * expf(s_pad - m);
    const float denom = dloc + w_pad;
    __syncwarp();

    float4 acc = make_float4(0.f, 0.f, 0.f, 0.f);
    for (int p = p_start; p < p_end; p++) {
        const float w = sc[h][p];
        const float4 v4 = *(const float4*)(Vc + (lo + p) * DM + base);
        acc.x += w * v4.x; acc.y += w * v4.y; acc.z += w * v4.z; acc.w += w * v4.w;
    }
    if (n_pad > 0) {
        const float4 vb4 = *(const float4*)(vb + base);
        acc.x += w_pad * vb4.x; acc.y += w_pad * vb4.y;
        acc.z += w_pad * vb4.z; acc.w += w_pad * vb4.w;
    }
    const float inv = 1.f / denom;
    float4 o = make_float4(acc.x * inv, acc.y * inv, acc.z * inv, acc.w * inv);
    *(uint4*)(g_O_tf[a] + i * DM + base) = cvt4(o);
}

// ---------------------------------------------------------------------------
extern "C" void kernel_launch(void* const* d_in, const int* in_sizes, int n_in,
                              void* d_out, int out_size) {
    (void)in_sizes; (void)n_in; (void)out_size;

    const float* images   = (const float*)d_in[0];
    const float* captions = (const float*)d_in[1];
    const float* tp_w = (const float*)d_in[3];
    const float* tp_b = (const float*)d_in[4];
    const float* ip_w = (const float*)d_in[5];
    const float* ip_b = (const float*)d_in[6];
    const float* ia[8]; for (int k = 0; k < 8; k++) ia[k] = (const float*)d_in[7 + k];
    const float* ta[8]; for (int k = 0; k < 8; k++) ta[k] = (const float*)d_in[15 + k];
    float* out = (float*)d_out;

    float *txt, *img, *Qb, *Kb, *Vb;
    unsigned *txt_tf, *img_tf, *Otf, *wtf, *cap_tf, *im_tf;
    cudaGetSymbolAddress((void**)&txt, g_txt);
    cudaGetSymbolAddress((void**)&img, g_img);
    cudaGetSymbolAddress((void**)&txt_tf, g_txt_tf);
    cudaGetSymbolAddress((void**)&img_tf, g_img_tf);
    cudaGetSymbolAddress((void**)&Qb, g_Q);
    cudaGetSymbolAddress((void**)&Kb, g_K);
    cudaGetSymbolAddress((void**)&Vb, g_V);
    cudaGetSymbolAddress((void**)&Otf, g_O_tf);
    cudaGetSymbolAddress((void**)&wtf, g_w_tf);
    cudaGetSymbolAddress((void**)&cap_tf, g_cap_tf);
    cudaGetSymbolAddress((void**)&im_tf, g_im_tf);

    // weight scratch slots: 0:tp 1:ip 2..5: ia q,k,v,o  6..9: ta q,k,v,o
    unsigned* wts[10];
    for (int s = 0; s < 10; s++) wts[s] = wtf + s * (DM * DM);

    // ---- launch 0: bulk tf32 conversion ----
    {
        ConvArgs ca{};
        const float* srcs[12] = { tp_w, ip_w, ia[0], ia[2], ia[4], ia[6],
                                  ta[0], ta[2], ta[4], ta[6], captions, images };
        unsigned*    dsts[12] = { wts[0], wts[1], wts[2], wts[3], wts[4], wts[5],
                                  wts[6], wts[7], wts[8], wts[9], cap_tf, im_tf };
        int ns[12] = { DM * 768, DM * DM, DM * DM, DM * DM, DM * DM, DM * DM,
                       DM * DM, DM * DM, DM * DM, DM * DM, NQ * 768, NQ * DM };
        for (int s = 0; s < 12; s++) { ca.src[s] = srcs[s]; ca.dst[s] = dsts[s]; ca.n4[s] = ns[s] / 4; }
        conv_tf32_kernel<<<dim3(64, 12), 256>>>(ca);
    }

    const dim3 blk(128);
    const int GX = DM / 64;   // 16
    const int GY = NQ / 64;   // 8
    const int SMEM = NSTAGE * TILE_WORDS * 2 * 4;  // 55296 B
    cudaFuncSetAttribute(gemm_tf32_kernel, cudaFuncAttributeMaxDynamicSharedMemorySize, SMEM);

    // ---- launch 1: input projections (z=2), dual-write f32 + tf32 ----
    {
        GemmArgs ar{};
        ar.A[0] = cap_tf; ar.W[0] = wts[0]; ar.bias[0] = tp_b; ar.resid[0] = nullptr;
        ar.C[0] = txt; ar.Ctf[0] = txt_tf; ar.K[0] = 768;
        ar.A[1] = im_tf;  ar.W[1] = wts[1]; ar.bias[1] = ip_b; ar.resid[1] = nullptr;
        ar.C[1] = img; ar.Ctf[1] = img_tf; ar.K[1] = 1024;
        gemm_tf32_kernel<<<dim3(GX, GY, 2), blk, SMEM>>>(ar);
    }

    // ---- launch 2: six QKV projections (z=6) ----
    {
        GemmArgs ar{};
        const unsigned* Aarr[6] = { img_tf, txt_tf, txt_tf, txt_tf, img_tf, img_tf };
        const unsigned* Warr[6] = { wts[2], wts[3], wts[4], wts[6], wts[7], wts[8] };
        const float*    Barr[6] = { ia[1], ia[3], ia[5], ta[1], ta[3], ta[5] };
        float*          Carr[6] = { Qb, Kb, Vb, Qb + NEL, Kb + NEL, Vb + NEL };
        for (int s = 0; s < 6; s++) {
            ar.A[s] = Aarr[s]; ar.W[s] = Warr[s]; ar.bias[s] = Barr[s];
            ar.resid[s] = nullptr; ar.C[s] = Carr[s]; ar.Ctf[s] = nullptr; ar.K[s] = 1024;
        }
        gemm_tf32_kernel<<<dim3(GX, GY, 6), blk, SMEM>>>(ar);
    }

    // ---- launch 3: sliding-window attention (writes tf32 O) ----
    swattn_kernel<<<dim3(NQ, 2), 256>>>(ia[3], ia[5], ta[3], ta[5]);

    // ---- launch 4: output projections + residual (z=2) ----
    {
        GemmArgs ar{};
        ar.A[0] = Otf;       ar.W[0] = wts[5]; ar.bias[0] = ia[7]; ar.resid[0] = img;
        ar.C[0] = out;       ar.Ctf[0] = nullptr; ar.K[0] = 1024;
        ar.A[1] = Otf + NEL; ar.W[1] = wts[9]; ar.bias[1] = ta[7]; ar.resid[1] = txt;
        ar.C[1] = out + NEL; ar.Ctf[1] = nullptr; ar.K[1] = 1024;
        gemm_tf32_kernel<<<dim3(GX, GY, 2), blk, SMEM>>>(ar);
    }
}